// round 17
// baseline (speedup 1.0000x reference)
#include <cuda_runtime.h>
#include <math.h>

#define BB 4
#define CC 64
#define LL 16384
#define BL 65536
#define DI 128
#define DS 16
#define NKF 65
#define NIMG 256
#define NCHK 64
#define CHKS 256
#define FPIX (NKF*128)   // 8320 freq pixels per image

__device__ float d_xz [BL*256];
__device__ float d_xc [BL*DI];
__device__ float d_dbc[BL*36];
__device__ float d_dt [BL*DI];
__device__ float d_hloc[BB*DI*NCHK*DS];
__device__ float d_cd  [BB*DI*NCHK];
__device__ float d_Hst [BB*DI*NCHK*DS];
__device__ float d_ygt [BB*DI*LL];
__device__ float d_xsp [BB*CC*LL];
__device__ float d_RT  [32768*130];
__device__ float d_Cre [NIMG*FPIX];
__device__ float d_Cim [NIMG*FPIX];
__device__ float d_mag [NIMG*FPIX];
__device__ float d_Zr  [NIMG*FPIX];
__device__ float d_Zi  [NIMG*FPIX];
__device__ float d_Yr  [NIMG*FPIX];
__device__ float d_Yi  [NIMG*FPIX];
__device__ float d_xfr [BB*CC*LL];
__device__ float d_TW1 [128*130];
__device__ float d_TCOS[128*128];
__device__ float d_TSIN[128*128];
__device__ float d_IRW1[NKF*128];
__device__ float d_IRW2[NKF*128];

__global__ void gen_tables() {
    int i = blockIdx.x*256 + threadIdx.x;
    if (i < 128*130) {
        int w = i/130, j = i%130;
        int k = (j < NKF) ? j : j-NKF;
        float s,c; sincospif((float)((w*k)&127)/64.0f, &s, &c);
        d_TW1[i] = (j < NKF) ? c : -s;
    }
    if (i < 128*128) {
        int u = i/128, h = i%128;
        float s,c; sincospif((float)((u*h)&127)/64.0f, &s, &c);
        d_TCOS[i]=c; d_TSIN[i]=s;
    }
    if (i < NKF*128) {
        int kf = i/128, w = i%128;
        float a = (kf==0 || kf==64) ? 1.0f : 2.0f;
        float s,c; sincospif((float)((kf*w)&127)/64.0f, &s, &c);
        d_IRW1[i] =  a*c*(1.0f/16384.0f);
        d_IRW2[i] = -a*s*(1.0f/16384.0f);
    }
}

// C[m,n] = sum_k A[m,k]*B[k,n] (+ A2[m,k]*B2[k,n] if DUAL)
// Block tile: (TM*16) x 64, microtile TM x 4 on 16x16 threads.
// biasMode: 0=none, 1=bias[n], 2=bias[m], 3=residual matrix add (bias has C layout)
template<bool DUAL, int TM>
__global__ void __launch_bounds__(256, 3)
sgemm(const float* __restrict__ A, const float* __restrict__ A2,
      int lda_m, int lda_k, int sA,
      const float* __restrict__ B, const float* __restrict__ B2,
      int ldb_k, int ldb_n, int sB,
      float* __restrict__ C, int ldc, int sC,
      int M, int N, int K,
      const float* __restrict__ bias, int biasMode, int doRelu)
{
    constexpr int BM = TM*16;
    __shared__ float As[16][BM+4], Bs[16][68];
    __shared__ float As2[DUAL?16:1][DUAL?(BM+4):1], Bs2[DUAL?16:1][DUAL?68:1];
    int bz = blockIdx.z;
    const float* Ab  = A + (size_t)bz*sA;
    const float* Bb  = B + (size_t)bz*sB;
    const float* A2b = DUAL ? (A2 + (size_t)bz*sA) : A;
    const float* B2b = DUAL ? (B2 + (size_t)bz*sB) : B;
    float* Cb = C + (size_t)bz*sC;
    int m0 = blockIdx.y*BM, n0 = blockIdx.x<<6;
    int tid = threadIdx.x, tx = tid&15, ty = tid>>4;
    float acc[TM][4];
#pragma unroll
    for (int i=0;i<TM;i++)
#pragma unroll
        for (int j=0;j<4;j++) acc[i][j]=0.f;

    for (int k0 = 0; k0 < K; k0 += 16) {
        if (lda_k == 1) {
            int kl = tid&15, ml0 = tid>>4;
#pragma unroll
            for (int i=0;i<TM;i++) {
                int ml = ml0 + (i<<4), m = m0+ml, k = k0+kl;
                bool ok = (m<M)&&(k<K);
                As[kl][ml] = ok ? Ab[(size_t)m*lda_m + k] : 0.f;
                if (DUAL) As2[kl][ml] = ok ? A2b[(size_t)m*lda_m + k] : 0.f;
            }
        } else {
#pragma unroll
            for (int i=0;i<TM;i++) {
                int idx = tid + i*256;
                int ml = idx % BM, kl = idx / BM;
                int m = m0+ml, k = k0+kl;
                bool ok = (m<M)&&(k<K);
                As[kl][ml] = ok ? Ab[(size_t)m*lda_m + (size_t)k*lda_k] : 0.f;
                if (DUAL) As2[kl][ml] = ok ? A2b[(size_t)m*lda_m + (size_t)k*lda_k] : 0.f;
            }
        }
        if (ldb_n == 1) {
            int nl = tid&63, kl0 = tid>>6;
#pragma unroll
            for (int i=0;i<4;i++) {
                int kl = kl0 + (i<<2), n = n0+nl, k = k0+kl;
                bool ok = (k<K)&&(n<N);
                Bs[kl][nl] = ok ? Bb[(size_t)k*ldb_k + n] : 0.f;
                if (DUAL) Bs2[kl][nl] = ok ? B2b[(size_t)k*ldb_k + n] : 0.f;
            }
        } else {
            int kl = tid&15, nl0 = tid>>4;
#pragma unroll
            for (int i=0;i<4;i++) {
                int nl = nl0 + (i<<4), n = n0+nl, k = k0+kl;
                bool ok = (k<K)&&(n<N);
                Bs[kl][nl] = ok ? Bb[(size_t)k*ldb_k + (size_t)n*ldb_n] : 0.f;
                if (DUAL) Bs2[kl][nl] = ok ? B2b[(size_t)k*ldb_k + (size_t)n*ldb_n] : 0.f;
            }
        }
        __syncthreads();
#pragma unroll
        for (int kk=0; kk<16; kk++) {
            float a[TM], b[4];
#pragma unroll
            for (int i=0;i<TM;i+=4) *(float4*)&a[i] = *(const float4*)&As[kk][ty*TM+i];
            *(float4*)&b[0] = *(const float4*)&Bs[kk][tx<<2];
#pragma unroll
            for (int i=0;i<TM;i++)
#pragma unroll
                for (int j=0;j<4;j++) acc[i][j] = fmaf(a[i], b[j], acc[i][j]);
            if (DUAL) {
                float a2[TM], b2[4];
#pragma unroll
                for (int i=0;i<TM;i+=4) *(float4*)&a2[i] = *(const float4*)&As2[kk][ty*TM+i];
                *(float4*)&b2[0] = *(const float4*)&Bs2[kk][tx<<2];
#pragma unroll
                for (int i=0;i<TM;i++)
#pragma unroll
                    for (int j=0;j<4;j++) acc[i][j] = fmaf(a2[i], b2[j], acc[i][j]);
            }
        }
        __syncthreads();
    }
#pragma unroll
    for (int i=0;i<TM;i++) {
        int m = m0 + ty*TM + i;
        if (m >= M) continue;
#pragma unroll
        for (int j=0;j<4;j++) {
            int n = n0 + (tx<<2) + j;
            if (n >= N) continue;
            float v = acc[i][j];
            if (biasMode == 1) v += bias[n];
            else if (biasMode == 2) v += bias[m];
            else if (biasMode == 3) v += bias[(size_t)bz*sC + (size_t)m*ldc + n];
            if (doRelu) v = fmaxf(v, 0.f);
            Cb[(size_t)m*ldc + n] = v;
        }
    }
}

// Two-head GEMM: C1 = A1@B + b1, C2 = A2@B + b2 sharing B tiles.
__global__ void __launch_bounds__(256, 3)
head2_k(const float* __restrict__ A1, const float* __restrict__ A2,
        const float* __restrict__ B, int sB,
        const float* __restrict__ b1, const float* __restrict__ b2,
        float* __restrict__ C1, float* __restrict__ C2, int sC)
{
    __shared__ float As1[16][68], As2[16][68], Bs[16][68];
    int bz = blockIdx.z;
    const float* Bb = B + (size_t)bz*sB;
    int n0 = blockIdx.x<<6;
    int tid = threadIdx.x, tx = tid&15, ty = tid>>4;
    float ac1[4][4], ac2[4][4];
#pragma unroll
    for (int i=0;i<4;i++)
#pragma unroll
        for (int j=0;j<4;j++) { ac1[i][j]=0.f; ac2[i][j]=0.f; }

    for (int k0 = 0; k0 < CC; k0 += 16) {
        {
            int kl = tid&15, ml0 = tid>>4;
#pragma unroll
            for (int i=0;i<4;i++) {
                int ml = ml0 + (i<<4), k = k0+kl;
                As1[kl][ml] = A1[(size_t)ml*CC + k];
                As2[kl][ml] = A2[(size_t)ml*CC + k];
            }
        }
        {
            int nl = tid&63, kl0 = tid>>6;
#pragma unroll
            for (int i=0;i<4;i++) {
                int kl = kl0 + (i<<2), n = n0+nl, k = k0+kl;
                Bs[kl][nl] = Bb[(size_t)k*LL + n];
            }
        }
        __syncthreads();
#pragma unroll
        for (int kk=0; kk<16; kk++) {
            float4 a1v = *(const float4*)&As1[kk][ty<<2];
            float4 a2v = *(const float4*)&As2[kk][ty<<2];
            float4 bv  = *(const float4*)&Bs[kk][tx<<2];
            float a1[4]={a1v.x,a1v.y,a1v.z,a1v.w};
            float a2[4]={a2v.x,a2v.y,a2v.z,a2v.w};
            float b[4]={bv.x,bv.y,bv.z,bv.w};
#pragma unroll
            for (int i=0;i<4;i++)
#pragma unroll
                for (int j=0;j<4;j++) {
                    ac1[i][j] = fmaf(a1[i], b[j], ac1[i][j]);
                    ac2[i][j] = fmaf(a2[i], b[j], ac2[i][j]);
                }
        }
        __syncthreads();
    }
    float* o1 = C1 + (size_t)bz*sC;
    float* o2 = C2 + (size_t)bz*sC;
#pragma unroll
    for (int i=0;i<4;i++) {
        int m = (ty<<2) + i;
        float bb1 = b1[m], bb2 = b2[m];
#pragma unroll
        for (int j=0;j<4;j++) {
            int n = n0 + (tx<<2) + j;
            o1[(size_t)m*LL + n] = ac1[i][j] + bb1;
            o2[(size_t)m*LL + n] = ac2[i][j] + bb2;
        }
    }
}

// ---------------------------------------------------------------------------
// Fused frequency-mix + phase kernel. One block = 32 pixels x all 64 channels.
//   M1 = relu(W1 @ mag + b1)         (M1 stays in smem)
//   M2 = W2 @ M1 + b2                (in registers)
//   Zr,Zi = phase-rotate(Cre,Cim,mag) scaled by M2
// ---------------------------------------------------------------------------
__global__ void __launch_bounds__(256)
mixphase_k(const float* __restrict__ W1, const float* __restrict__ b1,
           const float* __restrict__ W2, const float* __restrict__ b2,
           const float* __restrict__ mag, const float* __restrict__ Cre,
           const float* __restrict__ Cim,
           float* __restrict__ Zr, float* __restrict__ Zi)
{
    __shared__ float Ws[64][68];   // W (k-major): Ws[k][m]
    __shared__ float Ts[64][36];   // input tile: Ts[k][n]
    __shared__ float M1s[64][36];  // intermediate: M1s[k][n]
    int b  = blockIdx.z;
    int p0 = blockIdx.x*32;
    int tid = threadIdx.x, tx = tid&15, ty = tid>>4;

    // load W1 (Ws[k][m] = W1[m*64+k]) and mag tile (Ts[k][n])
    for (int i = tid; i < 64*64; i += 256) {
        int m = i >> 6, k = i & 63;
        Ws[k][m] = W1[i];
    }
    for (int i = tid; i < 64*32; i += 256) {
        int k = i >> 5, n = i & 31;
        Ts[k][n] = mag[((size_t)(b*64+k))*FPIX + p0 + n];
    }
    __syncthreads();

    // phase 1: acc = W1 @ mag-tile  (thread: 4 m x 2 n)
    float acc[4][2];
#pragma unroll
    for (int i=0;i<4;i++) { acc[i][0]=0.f; acc[i][1]=0.f; }
    for (int kk=0; kk<64; kk++) {
        float4 av = *(const float4*)&Ws[kk][ty<<2];
        float2 bv = *(const float2*)&Ts[kk][tx<<1];
        float a[4]={av.x,av.y,av.z,av.w};
#pragma unroll
        for (int i=0;i<4;i++) {
            acc[i][0] = fmaf(a[i], bv.x, acc[i][0]);
            acc[i][1] = fmaf(a[i], bv.y, acc[i][1]);
        }
    }
    __syncthreads();   // done reading Ws (W1)
    // write M1 = relu(acc + b1) into smem; reload Ws with W2
#pragma unroll
    for (int i=0;i<4;i++) {
        int m = (ty<<2)+i;
        float bb = b1[m];
        M1s[m][(tx<<1)  ] = fmaxf(acc[i][0]+bb, 0.f);
        M1s[m][(tx<<1)+1] = fmaxf(acc[i][1]+bb, 0.f);
    }
    for (int i = tid; i < 64*64; i += 256) {
        int m = i >> 6, k = i & 63;
        Ws[k][m] = W2[i];
    }
    __syncthreads();

    // phase 2: acc = W2 @ M1
#pragma unroll
    for (int i=0;i<4;i++) { acc[i][0]=0.f; acc[i][1]=0.f; }
    for (int kk=0; kk<64; kk++) {
        float4 av = *(const float4*)&Ws[kk][ty<<2];
        float2 bv = *(const float2*)&M1s[kk][tx<<1];
        float a[4]={av.x,av.y,av.z,av.w};
#pragma unroll
        for (int i=0;i<4;i++) {
            acc[i][0] = fmaf(a[i], bv.x, acc[i][0]);
            acc[i][1] = fmaf(a[i], bv.y, acc[i][1]);
        }
    }
    // epilogue: bias + phase rotation
#pragma unroll
    for (int i=0;i<4;i++) {
        int m = (ty<<2)+i;
        float bb = b2[m];
#pragma unroll
        for (int j=0;j<2;j++) {
            int n = (tx<<1)+j;
            size_t idx = ((size_t)(b*64+m))*FPIX + p0 + n;
            float m2 = acc[i][j] + bb;
            float mg = mag[idx];
            if (mg > 1e-20f) {
                float sc = m2/mg;
                Zr[idx] = Cre[idx]*sc;
                Zi[idx] = Cim[idx]*sc;
            } else { Zr[idx] = m2; Zi[idx] = 0.f; }
        }
    }
}

// ---------------------------------------------------------------------------
// Complex GEMM: Cr = Ac@Br + S1*As@Bi ; Ci = Ac@Bi - S1*As@Br (+ optional mag)
// ---------------------------------------------------------------------------
template<int S1, bool WMAG>
__global__ void __launch_bounds__(256, 3)
cgemm(const float* __restrict__ Ac, const float* __restrict__ Asn,
      const float* __restrict__ Br, const float* __restrict__ Bi, int ldbk, int sB,
      float* __restrict__ outR, float* __restrict__ outI, float* __restrict__ outM,
      int ldc, int sC, int M, int N, int K)
{
    __shared__ float Acs[16][68], Ass[16][68], Brs[16][68], Bis[16][68];
    int bz = blockIdx.z;
    const float* BrB = Br + (size_t)bz*sB;
    const float* BiB = Bi + (size_t)bz*sB;
    int m0 = blockIdx.y<<6, n0 = blockIdx.x<<6;
    int tid = threadIdx.x, tx = tid&15, ty = tid>>4;
    float aR[4][4], aI[4][4];
#pragma unroll
    for (int i=0;i<4;i++)
#pragma unroll
        for (int j=0;j<4;j++) { aR[i][j]=0.f; aI[i][j]=0.f; }

    for (int k0 = 0; k0 < K; k0 += 16) {
        {
            int kl = tid&15, ml0 = tid>>4;
#pragma unroll
            for (int i=0;i<4;i++) {
                int ml = ml0 + (i<<4), m = m0+ml, k = k0+kl;
                bool ok = (m<M);
                Acs[kl][ml] = ok ? Ac [(size_t)m*128 + k] : 0.f;
                Ass[kl][ml] = ok ? Asn[(size_t)m*128 + k] : 0.f;
            }
        }
        {
            int nl = tid&63, kl0 = tid>>6;
#pragma unroll
            for (int i=0;i<4;i++) {
                int kl = kl0 + (i<<2), n = n0+nl, k = k0+kl;
                bool ok = (n<N);
                Brs[kl][nl] = ok ? BrB[(size_t)k*ldbk + n] : 0.f;
                Bis[kl][nl] = ok ? BiB[(size_t)k*ldbk + n] : 0.f;
            }
        }
        __syncthreads();
#pragma unroll
        for (int kk=0; kk<16; kk++) {
            float4 acv = *(const float4*)&Acs[kk][ty<<2];
            float4 asv = *(const float4*)&Ass[kk][ty<<2];
            float4 brv = *(const float4*)&Brs[kk][tx<<2];
            float4 biv = *(const float4*)&Bis[kk][tx<<2];
            float ac[4]={acv.x,acv.y,acv.z,acv.w};
            float as[4]={asv.x,asv.y,asv.z,asv.w};
            float br[4]={brv.x,brv.y,brv.z,brv.w};
            float bi[4]={biv.x,biv.y,biv.z,biv.w};
            float sbi[4], sbr[4];
#pragma unroll
            for (int j=0;j<4;j++) {
                sbi[j] = (S1>0) ? bi[j] : -bi[j];
                sbr[j] = (S1>0) ? -br[j] : br[j];
            }
#pragma unroll
            for (int i=0;i<4;i++)
#pragma unroll
                for (int j=0;j<4;j++) {
                    aR[i][j] = fmaf(as[i], sbi[j], fmaf(ac[i], br[j], aR[i][j]));
                    aI[i][j] = fmaf(as[i], sbr[j], fmaf(ac[i], bi[j], aI[i][j]));
                }
        }
        __syncthreads();
    }
    float* oR = outR + (size_t)bz*sC;
    float* oI = outI + (size_t)bz*sC;
    float* oM = WMAG ? (outM + (size_t)bz*sC) : outR;
#pragma unroll
    for (int i=0;i<4;i++) {
        int m = m0 + (ty<<2) + i;
        if (m >= M) continue;
#pragma unroll
        for (int j=0;j<4;j++) {
            int n = n0 + (tx<<2) + j;
            if (n >= N) continue;
            float r = aR[i][j], im = aI[i][j];
            oR[(size_t)m*ldc + n] = r;
            oI[(size_t)m*ldc + n] = im;
            if (WMAG) oM[(size_t)m*ldc + n] = sqrtf(r*r + im*im);
        }
    }
}

// Complex Nyquist column (kf=64): warp per output u; writes re, im (+mag).
template<int S1, bool WMAG>
__global__ void cnyq_k(const float* __restrict__ Ac, const float* __restrict__ Asn,
                       const float* __restrict__ Br, const float* __restrict__ Bi,
                       int ldb, int sB,
                       float* __restrict__ outR, float* __restrict__ outI,
                       float* __restrict__ outM, int sC)
{
    int w = (blockIdx.x*256 + threadIdx.x) >> 5;
    int lane = threadIdx.x & 31;
    int img = w >> 7, u = w & 127;
    const float* br = Br + (size_t)img*sB;
    const float* bi = Bi + (size_t)img*sB;
    float sr = 0.f, si = 0.f;
#pragma unroll
    for (int kk=0; kk<4; kk++) {
        int k = lane + kk*32;
        float ac = Ac[u*128+k], as = Asn[u*128+k];
        float vr = br[(size_t)k*ldb], vi = bi[(size_t)k*ldb];
        sr += ac*vr + ((S1>0) ? as*vi : -as*vi);
        si += ac*vi - ((S1>0) ? as*vr : -as*vr);
    }
#pragma unroll
    for (int o=16; o>=1; o>>=1) {
        sr += __shfl_xor_sync(0xffffffffu, sr, o);
        si += __shfl_xor_sync(0xffffffffu, si, o);
    }
    if (lane == 0) {
        size_t idx = (size_t)img*sC + u*65 + 64;
        outR[idx] = sr;
        outI[idx] = si;
        if (WMAG) outM[idx] = sqrtf(sr*sr + si*si);
    }
}

// rfft columns 128,129 of the 130-wide row transform, warp-per-output.
__global__ void rfft_tail_k(const float* __restrict__ x, float* __restrict__ RT)
{
    int w = (blockIdx.x*256 + threadIdx.x) >> 5;
    int lane = threadIdx.x & 31;
    int row = w >> 1, j = 128 + (w & 1);
    const float* xr = x + (size_t)row*128;
    float s = 0.f;
#pragma unroll
    for (int kk=0; kk<4; kk++) {
        int k = lane + kk*32;
        s += xr[k]*d_TW1[k*130+j];
    }
#pragma unroll
    for (int o=16; o>=1; o>>=1) s += __shfl_xor_sync(0xffffffffu, s, o);
    if (lane == 0) RT[(size_t)row*130 + j] = s;
}

__global__ void conv_silu_k(const float* __restrict__ xz, const float* __restrict__ cw,
                            const float* __restrict__ cb, float* __restrict__ xc)
{
    int idx = blockIdx.x*256 + threadIdx.x;
    if (idx >= BL*DI) return;
    int d = idx & 127, bl = idx >> 7, l = bl & (LL-1);
    size_t base = (size_t)bl*256 + d;
    float acc = cb[d];
#pragma unroll
    for (int k=0;k<4;k++) {
        int lsrc = l - 3 + k;
        float v = (lsrc >= 0) ? xz[base + (size_t)(k-3)*256] : 0.f;
        acc = fmaf(cw[d*4+k], v, acc);
    }
    float sig = 1.f/(1.f+__expf(-acc));
    xc[idx] = acc*sig;
}

__global__ void dt_proj_k(const float* __restrict__ dbc, const float* __restrict__ Wdt,
                          const float* __restrict__ bdt, float* __restrict__ dt)
{
    int idx = blockIdx.x*256 + threadIdx.x;
    if (idx >= BL*DI) return;
    int d = idx & 127, bl = idx >> 7;
    const float* row = dbc + (size_t)bl*36;
    float s = bdt[d];
#pragma unroll
    for (int r=0;r<4;r++) s = fmaf(row[r], Wdt[r*128+d], s);
    dt[idx] = (s > 20.f) ? s : log1pf(__expf(s));
}

__global__ void scan1_k(const float* __restrict__ dt, const float* __restrict__ xc,
                        const float* __restrict__ dbc, const float* __restrict__ A_log,
                        float* __restrict__ hloc, float* __restrict__ cdout)
{
    int warp = threadIdx.x >> 5;
    int wg   = (blockIdx.x<<3) + warp;
    int lane = threadIdx.x & 31;
    int s = lane & 15, half = lane >> 4;
    int dpair = wg & 63, chunk = (wg>>6) & 63, b = wg>>12;
    int d = (dpair<<1) + half;
    float Aval = -__expf(A_log[d*16+s]);
    float h = 0.f, cd = 0.f;
    size_t rowbase = (size_t)b*LL + (chunk<<8);
    const float* dtp = dt  + rowbase*128 + d;
    const float* xcp = xc  + rowbase*128 + d;
    const float* bp  = dbc + rowbase*36 + 4 + s;
#pragma unroll 8
    for (int t=0;t<CHKS;t++) {
        float dtv = dtp[t*128], xcv = xcp[t*128], Bv = bp[t*36];
        h = fmaf(h, __expf(dtv*Aval), dtv*xcv*Bv);
        cd += dtv;
    }
    int cidx = (b*128+d)*NCHK + chunk;
    hloc[cidx*16+s] = h;
    if (s == 0 ) cdout[cidx] = cd;
}

__global__ void carry_k(const float* __restrict__ hloc, const float* __restrict__ cd,
                        const float* __restrict__ A_log, float* __restrict__ Hst)
{
    int idx = blockIdx.x*256 + threadIdx.x;
    if (idx >= BB*DI*DS) return;
    int s = idx & 15, d = (idx>>4)&127, b = idx>>11;
    float Aval = -__expf(A_log[d*16+s]);
    float H = 0.f;
    int base = (b*128+d)*NCHK;
    for (int c=0;c<NCHK;c++) {
        Hst[(base+c)*16+s] = H;
        H = fmaf(H, __expf(Aval*cd[base+c]), hloc[(base+c)*16+s]);
    }
}

__global__ void scan2_k(const float* __restrict__ dt, const float* __restrict__ xc,
                        const float* __restrict__ dbc, const float* __restrict__ A_log,
                        const float* __restrict__ Hst, const float* __restrict__ xz,
                        const float* __restrict__ Dvec, float* __restrict__ ygt)
{
    __shared__ float shy[8][2][CHKS];
    int warp = threadIdx.x >> 5;
    int wg   = (blockIdx.x<<3) + warp;
    int lane = threadIdx.x & 31;
    int s = lane & 15, half = lane >> 4;
    int dpair = wg & 63, chunk = (wg>>6) & 63, b = wg>>12;
    int d = (dpair<<1) + half;
    float Aval = -__expf(A_log[d*16+s]);
    float h = Hst[((b*128+d)*NCHK + chunk)*16 + s];
    float Dv = Dvec[d];
    int t0 = chunk<<8;
    size_t rowbase = (size_t)b*LL + t0;
    const float* dtp = dt  + rowbase*128 + d;
    const float* xcp = xc  + rowbase*128 + d;
    const float* bp  = dbc + rowbase*36 + 4 + s;
    const float* cp  = dbc + rowbase*36 + 20 + s;
    const float* zp  = xz  + rowbase*256 + 128 + d;
#pragma unroll 4
    for (int t=0;t<CHKS;t++) {
        float dtv = dtp[t*128], xcv = xcp[t*128], Bv = bp[t*36], Cv = cp[t*36];
        h = fmaf(h, __expf(dtv*Aval), dtv*xcv*Bv);
        float p = h*Cv;
        p += __shfl_xor_sync(0xffffffffu, p, 1);
        p += __shfl_xor_sync(0xffffffffu, p, 2);
        p += __shfl_xor_sync(0xffffffffu, p, 4);
        p += __shfl_xor_sync(0xffffffffu, p, 8);
        if (s == 0) {
            float zv = zp[(size_t)t*256];
            float y = fmaf(xcv, Dv, p);
            float sig = 1.f/(1.f+__expf(-zv));
            shy[warp][half][t] = y*zv*sig;
        }
    }
    __syncwarp();
#pragma unroll
    for (int r=0;r<2;r++) {
        int dd = (dpair<<1) + r;
        float* dst = ygt + ((size_t)b*128 + dd)*LL + t0;
        for (int t=lane;t<CHKS;t+=32) dst[t] = shy[warp][r][t];
    }
}

static void G(const float* A, const float* A2, int lam, int lak, int sA,
              const float* B, const float* B2, int lbk, int lbn, int sB,
              float* C, int ldc, int sC, int M, int N, int K, int batch,
              const float* bias, int bm, int relu)
{
    dim3 grid((N+63)>>6, (M+63)>>6, batch);
    if (A2) sgemm<true,4 ><<<grid,256>>>(A,A2,lam,lak,sA,B,B2,lbk,lbn,sB,C,ldc,sC,M,N,K,bias,bm,relu);
    else    sgemm<false,4><<<grid,256>>>(A,nullptr,lam,lak,sA,B,nullptr,lbk,lbn,sB,C,ldc,sC,M,N,K,bias,bm,relu);
}

static void G8(const float* A, int lam, int lak, int sA,
               const float* B, int lbk, int lbn, int sB,
               float* C, int ldc, int sC, int M, int N, int K, int batch,
               const float* bias, int bm, int relu)
{
    dim3 grid((N+63)>>6, (M+127)>>7, batch);
    sgemm<false,8><<<grid,256>>>(A,nullptr,lam,lak,sA,B,nullptr,lbk,lbn,sB,C,ldc,sC,M,N,K,bias,bm,relu);
}

extern "C" void kernel_launch(void* const* d_in, const int* in_sizes, int n_in,
                              void* d_out, int out_size)
{
    const float* x      = (const float*)d_in[0];
    const float* W_in   = (const float*)d_in[1];
    const float* conv_w = (const float*)d_in[2];
    const float* conv_b = (const float*)d_in[3];
    const float* W_xproj= (const float*)d_in[4];
    const float* W_dt   = (const float*)d_in[5];
    const float* b_dt   = (const float*)d_in[6];
    const float* A_log  = (const float*)d_in[7];
    const float* Dvec   = (const float*)d_in[8];
    const float* W_out  = (const float*)d_in[9];
    const float* Wf1    = (const float*)d_in[10];
    const float* bf1    = (const float*)d_in[11];
    const float* Wf2    = (const float*)d_in[12];
    const float* bf2    = (const float*)d_in[13];
    const float* W_enh  = (const float*)d_in[14];
    const float* b_enh  = (const float*)d_in[15];
    const float* W_seg  = (const float*)d_in[16];
    const float* b_seg  = (const float*)d_in[17];
    float* out = (float*)d_out;

    void* pv;
    cudaGetSymbolAddress(&pv, d_xz);   float* p_xz  = (float*)pv;
    cudaGetSymbolAddress(&pv, d_xc);   float* p_xc  = (float*)pv;
    cudaGetSymbolAddress(&pv, d_dbc);  float* p_dbc = (float*)pv;
    cudaGetSymbolAddress(&pv, d_dt);   float* p_dt  = (float*)pv;
    cudaGetSymbolAddress(&pv, d_hloc); float* p_hl  = (float*)pv;
    cudaGetSymbolAddress(&pv, d_cd);   float* p_cd  = (float*)pv;
    cudaGetSymbolAddress(&pv, d_Hst);  float* p_Hs  = (float*)pv;
    cudaGetSymbolAddress(&pv, d_ygt);  float* p_yg  = (float*)pv;
    cudaGetSymbolAddress(&pv, d_xsp);  float* p_xsp = (float*)pv;
    cudaGetSymbolAddress(&pv, d_RT);   float* p_RT  = (float*)pv;
    cudaGetSymbolAddress(&pv, d_Cre);  float* p_Cre = (float*)pv;
    cudaGetSymbolAddress(&pv, d_Cim);  float* p_Cim = (float*)pv;
    cudaGetSymbolAddress(&pv, d_mag);  float* p_mag = (float*)pv;
    cudaGetSymbolAddress(&pv, d_Zr);   float* p_Zr  = (float*)pv;
    cudaGetSymbolAddress(&pv, d_Zi);   float* p_Zi  = (float*)pv;
    cudaGetSymbolAddress(&pv, d_Yr);   float* p_Yr  = (float*)pv;
    cudaGetSymbolAddress(&pv, d_Yi);   float* p_Yi  = (float*)pv;
    cudaGetSymbolAddress(&pv, d_xfr);  float* p_xfr = (float*)pv;
    cudaGetSymbolAddress(&pv, d_TW1);  float* p_TW1 = (float*)pv;
    cudaGetSymbolAddress(&pv, d_TCOS); float* p_TC  = (float*)pv;
    cudaGetSymbolAddress(&pv, d_TSIN); float* p_TS  = (float*)pv;
    cudaGetSymbolAddress(&pv, d_IRW1); float* p_I1  = (float*)pv;
    cudaGetSymbolAddress(&pv, d_IRW2); float* p_I2  = (float*)pv;

    gen_tables<<<65, 256>>>();

    // ---- Mamba branch ----
    G8(x, 1, LL, CC*LL,  W_in, 256,1, 0,  p_xz, 256, LL*256,  LL, 256, CC, BB, 0,0,0);
    conv_silu_k<<<(BL*DI+255)/256,256>>>(p_xz, conv_w, conv_b, p_xc);
    G8(p_xc, 128,1,0,  W_xproj, 36,1,0,  p_dbc, 36,0,  BL, 36, 128, 1, 0,0,0);
    dt_proj_k<<<(BL*DI+255)/256,256>>>(p_dbc, W_dt, b_dt, p_dt);
    scan1_k<<<2048,256>>>(p_dt, p_xc, p_dbc, A_log, p_hl, p_cd);
    carry_k<<<32,256>>>(p_hl, p_cd, A_log, p_Hs);
    scan2_k<<<2048,256>>>(p_dt, p_xc, p_dbc, A_log, p_Hs, p_xz, Dvec, p_yg);
    G(W_out,0, 1, CC, 0,  p_yg,0, LL,1, DI*LL,  p_xsp, LL, CC*LL,  CC, LL, DI, BB, 0,0,0);

    // ---- Frequency branch ----
    G8(x, 128,1,0,  p_TW1, 130,1,0,  p_RT, 130,0,  32768, 128, 128, 1, 0,0,0);
    rfft_tail_k<<<8192,256>>>(x, p_RT);
    // column FFT: complex GEMM (re+im+mag), cnyq for col 64
    {
        dim3 grid(1, 2, NIMG);
        cgemm<1,true><<<grid,256>>>(p_TC, p_TS, p_RT, p_RT+65, 130, 128*130,
                                    p_Cre, p_Cim, p_mag, NKF, FPIX, 128, 64, 128);
    }
    cnyq_k<1,true><<<4096,256>>>(p_TC, p_TS, p_RT+64, p_RT+129, 130, 128*130,
                                 p_Cre, p_Cim, p_mag, FPIX);
    // fused channel-mix + phase rotation: mag -> Zr/Zi (no M1/M2 round-trips)
    {
        dim3 grid(FPIX/32, 1, BB);
        mixphase_k<<<grid,256>>>(Wf1, bf1, Wf2, bf2, p_mag, p_Cre, p_Cim, p_Zr, p_Zi);
    }
    // inverse column FFT
    {
        dim3 grid(1, 2, NIMG);
        cgemm<-1,false><<<grid,256>>>(p_TC, p_TS, p_Zr, p_Zi, NKF, FPIX,
                                      p_Yr, p_Yi, nullptr, NKF, FPIX, 128, 64, 128);
    }
    cnyq_k<-1,false><<<4096,256>>>(p_TC, p_TS, p_Zr+64, p_Zi+64, NKF, FPIX,
                                   p_Yr, p_Yi, nullptr, FPIX);
    // irfft rows + fused residual add of x_spatial
    G(p_Yr, p_Yi, NKF,1, FPIX,  p_I1, p_I2, 128,1, 0,  p_xfr, 128, LL,  128, 128, NKF, NIMG, p_xsp, 3, 0);

    // ---- Heads: fused dual-output GEMM ----
    {
        dim3 grid(LL/64, 1, BB);
        head2_k<<<grid,256>>>(W_enh, W_seg, p_xfr, CC*LL, b_enh, b_seg,
                              out, out + BB*CC*LL, CC*LL);
    }
}